// round 15
// baseline (speedup 1.0000x reference)
#include <cuda_runtime.h>
#include <cuda_fp16.h>
#include <math.h>
#include <stdint.h>

#define PI2F 6.28318530717958647692f

// ---------------- scratch (device globals; no allocation) ----------------
static __device__ float  g_conv[16*128*4096];      // conv2+BN+ReLU output
static __device__ float2 g_f   [16*128*4096];      // fft2 spectrum (read-only after K2)
static __device__ float  g_norm[16*128];           // per-(b,c) spectral L2 norm
static __device__ float2 g_attn[16*8*256];         // softmaxed attention (b,h,16,16)
static __device__ float2 g_outf[16*128*4096];      // cp-IDFT'd spectrum
static __device__ uint32_t g_xh[16*4096*128];      // X fp16 pairs, pixel-major: [b][hw][icp]
static __device__ uint32_t g_wsplit[36*4096];      // weight chunks fp16, pre-swizzled
static __device__ float2 g_gpart[8*128*256];       // partial gram sums [seg][bh][256]
static __device__ float  g_tq[16*4096*8];          // gate bottleneck activations [b][p][8]

// 16-pt inverse twiddles e^{+2*pi*i*t/16}
__constant__ float2 c_tw16[16] = {
  { 1.00000000f,  0.00000000f}, { 0.92387953f,  0.38268343f},
  { 0.70710678f,  0.70710678f}, { 0.38268343f,  0.92387953f},
  { 0.00000000f,  1.00000000f}, {-0.38268343f,  0.92387953f},
  {-0.70710678f,  0.70710678f}, {-0.92387953f,  0.38268343f},
  {-1.00000000f,  0.00000000f}, {-0.92387953f, -0.38268343f},
  {-0.70710678f, -0.70710678f}, {-0.38268343f, -0.92387953f},
  { 0.00000000f, -1.00000000f}, { 0.38268343f, -0.92387953f},
  { 0.70710678f, -0.70710678f}, { 0.92387953f, -0.38268343f}
};

// ================= helpers =================
__device__ __forceinline__ uint32_t smem_u32(const void* p){
  uint32_t a;
  asm("{ .reg .u64 t; cvta.to.shared.u64 t, %1; cvt.u32.u64 %0, t; }" : "=r"(a) : "l"(p));
  return a;
}
__device__ __forceinline__ uint32_t pack_h2(float v0, float v1){
  __half a0 = __float2half_rn(v0), a1 = __float2half_rn(v1);
  return (uint32_t)__half_as_ushort(a0) | ((uint32_t)__half_as_ushort(a1) << 16);
}
__device__ __forceinline__ void ldmx4(uint32_t* d, uint32_t addr){
  asm volatile("ldmatrix.sync.aligned.m8n8.x4.shared.b16 {%0,%1,%2,%3}, [%4];"
               : "=r"(d[0]), "=r"(d[1]), "=r"(d[2]), "=r"(d[3]) : "r"(addr));
}
__device__ __forceinline__ void mma16816h(float* d, const uint32_t* a, const uint32_t* b){
  asm volatile(
    "mma.sync.aligned.m16n8k16.row.col.f32.f16.f16.f32 "
    "{%0,%1,%2,%3}, {%4,%5,%6,%7}, {%8,%9}, {%0,%1,%2,%3};"
    : "+f"(d[0]), "+f"(d[1]), "+f"(d[2]), "+f"(d[3])
    : "r"(a[0]), "r"(a[1]), "r"(a[2]), "r"(a[3]), "r"(b[0]), "r"(b[1]));
}
__device__ __forceinline__ void cp16(uint32_t dst, const void* src, uint32_t sz){
  asm volatile("cp.async.cg.shared.global [%0], [%1], 16, %2;"
               :: "r"(dst), "l"(src), "r"(sz) : "memory");
}

// ---------------- K0a: pack X to fp16 pairs, pixel-major transpose ----------
__global__ void __launch_bounds__(256) k_xprep(const float* __restrict__ X){
  __shared__ float st[256][33];
  int b   = blockIdx.x >> 7;
  int hw0 = (blockIdx.x & 127) * 32;
  int tid = threadIdx.x;
  #pragma unroll 8
  for (int it = 0; it < 32; ++it){
    int idx = it*256 + tid;
    int ch = idx >> 5, w = idx & 31;
    st[ch][w] = X[((size_t)b*256 + ch)*4096 + hw0 + w];
  }
  __syncthreads();
  #pragma unroll 4
  for (int it = 0; it < 16; ++it){
    int idx = it*256 + tid;
    int w = idx >> 7, icp = idx & 127;
    g_xh[((size_t)b*4096 + hw0 + w)*128 + icp] = pack_h2(st[2*icp][w], st[2*icp + 1][w]);
  }
}

// ---------------- K0b: pack + pre-swizzle weights per chunk ----------------
__global__ void __launch_bounds__(256) k_wprep(const float* __restrict__ W){
  int idx = blockIdx.x*256 + threadIdx.x;     // 36*4096 = 147456
  int chunk = idx >> 12;
  int rem = idx & 4095;
  int oc = rem >> 5, icp = rem & 31;
  int tap = chunk >> 2, icb = (chunk & 3) << 6;
  int ic = icb + 2*icp;
  float v0 = W[(size_t)(oc*256 + ic)*9 + tap];
  float v1 = W[(size_t)(oc*256 + ic + 1)*9 + tap];
  uint32_t off = ((uint32_t)(oc*128 + icp*4)) ^ (((uint32_t)(oc & 7)) << 4);
  g_wsplit[(chunk*16384u + off) >> 2] = pack_h2(v0, v1);
}

// ---------------- K1: conv as fp16 HMMA implicit GEMM, 3-stage ring ---------
__global__ void __launch_bounds__(256) k_conv_mma(const float* __restrict__ cbp,
                                                  const float* __restrict__ bsc,
                                                  const float* __restrict__ bbi)
{
  extern __shared__ __align__(128) char sm[];
  __shared__ float s_prm[384];
  const int tid = threadIdx.x;
  const int wid = tid >> 5, lane = tid & 31;
  const int wm = wid & 3, wn = wid >> 2;
  const int b    = blockIdx.x >> 5;
  const int tile = blockIdx.x & 31;
  const int h0   = tile * 2;

  if (tid < 128){
    s_prm[tid]       = cbp[tid];
    s_prm[128 + tid] = bsc[tid];
    s_prm[256 + tid] = bbi[tid];
  }
  const uint32_t smb = smem_u32(sm);
  const int m = lane >> 3, r = lane & 7;
  const int fseg = tid & 7, fpr = tid >> 3;

  int rowA[2], xrA[2];
  #pragma unroll
  for (int mt=0; mt<2; ++mt){
    rowA[mt] = wm*32 + mt*16 + (m & 1)*8 + r;
    xrA[mt]  = (rowA[mt] & 7) << 4;
  }
  const int colAhalf = (m >> 1) * 16;
  int rowB[4], xrB[4];
  #pragma unroll
  for (int ntp=0; ntp<4; ++ntp){
    rowB[ntp] = wn*64 + ntp*16 + (m >> 1)*8 + r;
    xrB[ntp]  = (rowB[ntp] & 7) << 4;
  }
  const int colBhalf = (m & 1) * 16;

  float acc[2][8][4];
  #pragma unroll
  for (int i=0;i<2;i++)
    #pragma unroll
    for (int j=0;j<8;j++)
      #pragma unroll
      for (int q=0;q<4;q++) acc[i][j][q] = 0.f;

  auto fill = [&](int n, uint32_t sb){
    const int tap = n >> 2;
    const int icpg0 = (n & 3) << 5;
    const int dy = (tap / 3) * 3 - 3, dx = (tap % 3) * 3 - 3;
    #pragma unroll
    for (int it = 0; it < 4; ++it){
      int px = it*32 + fpr;
      int hh = h0 + (px >> 6) + dy;
      int ww = (px & 63) + dx;
      bool valid = ((unsigned)hh < 64u) && ((unsigned)ww < 64u);
      size_t gbase = (((size_t)b*4096) + (valid ? hh*64 + ww : 0))*128 + icpg0;
      uint32_t sz = valid ? 16u : 0u;
      uint32_t off = (uint32_t)(px*128) + (((uint32_t)(fseg*16)) ^ (((uint32_t)(px & 7)) << 4));
      cp16(smb + sb + off, (const char*)(g_xh + gbase) + fseg*16, sz);
    }
    const uint4* wsrc = (const uint4*)&g_wsplit[n * 4096];
    #pragma unroll
    for (int it = 0; it < 4; ++it){
      int idx = it*256 + tid;
      cp16(smb + sb + 16384 + idx*16, wsrc + idx, 16);
    }
    asm volatile("cp.async.commit_group;" ::: "memory");
  };

  fill(0, 0);
  fill(1, 32768);
  for (int n = 0; n < 36; ++n){
    const uint32_t sb = (uint32_t)(n % 3) * 32768u;
    if (n < 35){
      asm volatile("cp.async.wait_group 1;" ::: "memory");
    } else {
      asm volatile("cp.async.wait_group 0;" ::: "memory");
    }
    __syncthreads();

    #pragma unroll
    for (int kk = 0; kk < 4; ++kk){
      uint32_t ah[2][4];
      const int colA = kk*32 + colAhalf;
      #pragma unroll
      for (int mt=0; mt<2; ++mt){
        uint32_t aaddr = smb + sb + rowA[mt]*128 + (colA ^ xrA[mt]);
        ldmx4(ah[mt], aaddr);
      }
      const int colB = kk*32 + colBhalf;
      #pragma unroll
      for (int ntp=0; ntp<4; ++ntp){
        uint32_t bh[4];
        uint32_t baddr = smb + sb + 16384 + rowB[ntp]*128 + (colB ^ xrB[ntp]);
        ldmx4(bh, baddr);
        #pragma unroll
        for (int mt=0; mt<2; ++mt){
          #pragma unroll
          for (int hf=0; hf<2; ++hf)
            mma16816h(acc[mt][ntp*2 + hf], ah[mt], bh + hf*2);
        }
      }
    }
    if (n + 2 <= 35)
      fill(n + 2, (uint32_t)((n + 2) % 3) * 32768u);
  }

  const int g2 = lane >> 2, tig = lane & 3;
  float* outb = &g_conv[(size_t)b*128*4096 + h0*64];
  #pragma unroll
  for (int mt=0; mt<2; ++mt){
    int px0 = wm*32 + mt*16 + g2;
    #pragma unroll
    for (int nt=0; nt<8; ++nt){
      int oc0 = wn*64 + nt*8 + 2*tig;
      #pragma unroll
      for (int q=0; q<4; ++q){
        int px = px0 + (q >> 1)*8;
        int oc = oc0 + (q & 1);
        float v = (acc[mt][nt][q] + s_prm[oc]) * s_prm[128+oc] + s_prm[256+oc];
        outb[(size_t)oc*4096 + px] = fmaxf(v, 0.f);
      }
    }
  }
}

// ---------------- complex helpers ----------------
struct cpx { float x, y; };
__device__ __forceinline__ cpx mk(float a, float b){ cpx r; r.x=a; r.y=b; return r; }
__device__ __forceinline__ cpx cadd(cpx a, cpx b){ return mk(a.x+b.x, a.y+b.y); }
__device__ __forceinline__ cpx csub(cpx a, cpx b){ return mk(a.x-b.x, a.y-b.y); }
__device__ __forceinline__ cpx cmul(cpx a, cpx b){ return mk(a.x*b.x - a.y*b.y, a.x*b.y + a.y*b.x); }

template<int S>
__device__ __forceinline__ cpx mulJ(cpx a){
  return (S < 0) ? mk(a.y, -a.x) : mk(-a.y, a.x);
}
template<int S>
__device__ __forceinline__ cpx tw(int t, int N){
  t &= (N - 1);
  if (t > (N >> 1)) t -= N;
  float a = ((S < 0) ? -PI2F : PI2F) * (float)t / (float)N;
  float s, c;
  __sincosf(a, &s, &c);
  return mk(c, s);
}
template<int S>
__device__ __forceinline__ void dft8(cpx v[8]){
  const float r = 0.70710678118654752440f;
  cpx a0=cadd(v[0],v[4]), a1=csub(v[0],v[4]);
  cpx a2=cadd(v[2],v[6]), a3=csub(v[2],v[6]);
  cpx a4=cadd(v[1],v[5]), a5=csub(v[1],v[5]);
  cpx a6=cadd(v[3],v[7]), a7=csub(v[3],v[7]);
  cpx j3 = mulJ<S>(a3);
  cpx E0=cadd(a0,a2), E2=csub(a0,a2), E1=cadd(a1,j3), E3=csub(a1,j3);
  cpx j7 = mulJ<S>(a7);
  cpx O0=cadd(a4,a6), O2=csub(a4,a6), O1=cadd(a5,j7), O3=csub(a5,j7);
  cpx w1 = mk(r, (S<0)? -r : r);
  cpx w3 = mk(-r, (S<0)? -r : r);
  cpx t1 = cmul(O1, w1);
  cpx t2 = mulJ<S>(O2);
  cpx t3 = cmul(O3, w3);
  v[0]=cadd(E0,O0); v[4]=csub(E0,O0);
  v[1]=cadd(E1,t1); v[5]=csub(E1,t1);
  v[2]=cadd(E2,t2); v[6]=csub(E2,t2);
  v[3]=cadd(E3,t3); v[7]=csub(E3,t3);
}
// 64-pt DFT on float2 smem; elements at base[i*stride]; 8-thread group (lane l)
template<int S>
__device__ void fft64v(float2* base, int stride, int l){
  cpx v[8];
  #pragma unroll
  for (int j=0;j<8;j++){ float2 t = base[(l+8*j)*stride]; v[j]=mk(t.x, t.y); }
  dft8<S>(v);
  #pragma unroll
  for (int k=1;k<8;k++) v[k] = cmul(v[k], tw<S>(l*k, 64));
  __syncwarp();
  #pragma unroll
  for (int k=0;k<8;k++) base[(l*8+k)*stride] = make_float2(v[k].x, v[k].y);
  __syncwarp();
  #pragma unroll
  for (int j=0;j<8;j++){ float2 t = base[(j*8+l)*stride]; v[j]=mk(t.x, t.y); }
  dft8<S>(v);
  #pragma unroll
  for (int k=0;k<8;k++) base[(k*8+l)*stride] = make_float2(v[k].x, v[k].y);
  __syncthreads();
}

#define FFT_PITCH 66

// ---------------- K2: packed 2-channel forward fft2 + norms ----------------
__global__ void __launch_bounds__(512) k_fft2(){
  __shared__ float2 sc[64][FFT_PITCH];
  __shared__ float s_sum0, s_sum1;
  int bc2 = blockIdx.x;
  int tid = threadIdx.x;
  if (tid==0){ s_sum0 = 0.f; s_sum1 = 0.f; }
  const float* src0 = &g_conv[(size_t)(2*bc2)*4096];
  const float* src1 = src0 + 4096;
  for (int idx=tid; idx<4096; idx+=512)
    sc[idx>>6][idx&63] = make_float2(src0[idx], src1[idx]);
  __syncthreads();
  int g = tid>>3, l = tid&7;
  fft64v<-1>(&sc[0][g], FFT_PITCH, l);
  fft64v<-1>(&sc[g][0], 1,         l);
  float p0 = 0.f, p1 = 0.f;
  float2* f0 = &g_f[(size_t)(2*bc2)*4096];
  float2* f1 = f0 + 4096;
  for (int idx=tid; idx<4096; idx+=512){
    int kh = idx>>6, kw = idx&63;
    float2 Z  = sc[kh][kw];
    float2 Zm = sc[(64-kh)&63][(64-kw)&63];
    float2 F0 = make_float2(0.5f*(Z.x + Zm.x), 0.5f*(Z.y - Zm.y));
    float2 F1 = make_float2(0.5f*(Z.y + Zm.y), 0.5f*(Zm.x - Z.x));
    f0[idx] = F0; f1[idx] = F1;
    p0 = fmaf(F0.x, F0.x, p0); p0 = fmaf(F0.y, F0.y, p0);
    p1 = fmaf(F1.x, F1.x, p1); p1 = fmaf(F1.y, F1.y, p1);
  }
  #pragma unroll
  for (int s=16;s;s>>=1){
    p0 += __shfl_xor_sync(0xffffffffu, p0, s);
    p1 += __shfl_xor_sync(0xffffffffu, p1, s);
  }
  if ((tid&31)==0){ atomicAdd(&s_sum0, p0); atomicAdd(&s_sum1, p1); }
  __syncthreads();
  if (tid==0){
    g_norm[2*bc2]   = sqrtf(s_sum0);
    g_norm[2*bc2+1] = sqrtf(s_sum1);
  }
}

// ---------------- K3a: partial gram sums ----------
__global__ void __launch_bounds__(256) k_gram_part(){
  __shared__ float2 sQ[16][129];
  int bh  = blockIdx.x >> 3;
  int seg = blockIdx.x & 7;
  int tid = threadIdx.x;
  int i = tid >> 4, jj = tid & 15;
  float ax=0.f, ay=0.f;
  int ch0 = seg * 512;
  for (int ch = ch0; ch < ch0 + 512; ch += 128){
    for (int idx=tid; idx<2048; idx+=256)
      sQ[idx>>7][idx&127] = g_f[(bh*16 + (idx>>7))*4096 + ch + (idx&127)];
    __syncthreads();
    #pragma unroll 4
    for (int n=0;n<128;n++){
      float2 a = sQ[i][n], b = sQ[jj][n];
      ax = fmaf(a.x, b.x, ax); ax = fmaf(-a.y, b.y, ax);
      ay = fmaf(a.x, b.y, ay); ay = fmaf(a.y, b.x, ay);
    }
    __syncthreads();
  }
  g_gpart[(seg*128 + bh)*256 + tid] = make_float2(ax, ay);
}

// ---------------- K3b: reduce partials + normalize + dual softmax -----------
__global__ void __launch_bounds__(256) k_gram_fin(const float* __restrict__ temp){
  int bh = blockIdx.x;
  int tid = threadIdx.x;
  int i = tid >> 4, jj = tid & 15;
  float ax=0.f, ay=0.f;
  #pragma unroll
  for (int s=0;s<8;s++){
    float2 p = g_gpart[(s*128 + bh)*256 + tid];
    ax += p.x; ay += p.y;
  }
  float ni = fmaxf(g_norm[bh*16 + i],  1e-12f);
  float nj = fmaxf(g_norm[bh*16 + jj], 1e-12f);
  float sc = temp[bh & 7] / (ni*nj);
  float gr = ax*sc, gi = ay*sc;
  float mr = gr, mi = gi;
  #pragma unroll
  for (int m2=8;m2;m2>>=1){
    mr = fmaxf(mr, __shfl_xor_sync(0xffffffffu, mr, m2));
    mi = fmaxf(mi, __shfl_xor_sync(0xffffffffu, mi, m2));
  }
  float er = __expf(gr - mr), ei = __expf(gi - mi);
  float srn = er, sin_ = ei;
  #pragma unroll
  for (int m2=8;m2;m2>>=1){
    srn  += __shfl_xor_sync(0xffffffffu, srn, m2);
    sin_ += __shfl_xor_sync(0xffffffffu, sin_, m2);
  }
  g_attn[bh*256 + tid] = make_float2(er/srn, ei/sin_);
}

// ---------------- K4: apply attention + in-register 16-pt cp-IDFT ----------
__global__ void __launch_bounds__(256) k_apply(){
  __shared__ float2 sF[16][257];
  __shared__ float2 sA[256];
  int bh = blockIdx.x >> 3;
  int cq = blockIdx.x & 7;
  int tid = threadIdx.x;
  sA[tid] = g_attn[bh*256 + tid];
  int ch0 = cq * 512;
  for (int ch=ch0; ch<ch0+512; ch+=256){
    #pragma unroll
    for (int k=0;k<16;k++){
      int idx = tid + k*256;
      sF[idx>>8][idx&255] = g_f[(bh*16 + (idx>>8))*4096 + ch + (idx&255)];
    }
    __syncthreads();
    float2 acc[16];
    #pragma unroll
    for (int i=0;i<16;i++) acc[i] = make_float2(0.f, 0.f);
    #pragma unroll
    for (int j=0;j<16;j++){
      float2 fv = sF[j][tid];
      #pragma unroll
      for (int i=0;i<16;i++){
        float2 a = sA[i*16 + j];
        acc[i].x = fmaf(a.x, fv.x, acc[i].x); acc[i].x = fmaf(-a.y, fv.y, acc[i].x);
        acc[i].y = fmaf(a.x, fv.y, acc[i].y); acc[i].y = fmaf(a.y, fv.x, acc[i].y);
      }
    }
    float2 inner[4][4];
    #pragma unroll
    for (int j=0;j<4;j++){
      float2 x0 = acc[j], x1 = acc[j+4], x2 = acc[j+8], x3 = acc[j+12];
      float t0x = x0.x + x2.x, t0y = x0.y + x2.y;
      float t1x = x0.x - x2.x, t1y = x0.y - x2.y;
      float t2x = x1.x + x3.x, t2y = x1.y + x3.y;
      float t3x = -(x1.y - x3.y), t3y = x1.x - x3.x;
      inner[j][0] = make_float2(t0x + t2x, t0y + t2y);
      inner[j][1] = make_float2(t1x + t3x, t1y + t3y);
      inner[j][2] = make_float2(t0x - t2x, t0y - t2y);
      inner[j][3] = make_float2(t1x - t3x, t1y - t3y);
    }
    #pragma unroll
    for (int ip=0; ip<16; ip++){
      int p = ip & 3;
      float2 y = inner[0][p];
      #pragma unroll
      for (int j=1;j<4;j++){
        float2 w = c_tw16[(ip*j) & 15];
        float2 v = inner[j][p];
        y.x = fmaf(v.x, w.x, y.x); y.x = fmaf(-v.y, w.y, y.x);
        y.y = fmaf(v.x, w.y, y.y); y.y = fmaf( v.y, w.x, y.y);
      }
      g_outf[(bh*16 + ip)*4096 + ch + tid] = y;
    }
    __syncthreads();
  }
}

// ---------------- K5: 4096-pt IFFT per row + abs + residual -> out ----------
__global__ void __launch_bounds__(512) k_ifft4096(const float* __restrict__ x,
                                                  float* __restrict__ out){
  __shared__ float2 sc[64][FFT_PITCH];
  int row = blockIdx.x;
  int tid = threadIdx.x;
  const float2* base = &g_outf[(size_t)row*4096];
  for (int idx=tid; idx<4096; idx+=512)
    sc[idx>>6][idx&63] = base[idx];
  __syncthreads();
  int g = tid>>3, l = tid&7;
  fft64v<1>(&sc[0][g], FFT_PITCH, l);
  for (int idx=tid; idx<4096; idx+=512){
    int n2 = idx>>6, k1 = idx&63;
    cpx t = tw<1>(n2*k1, 4096);
    float2 vv = sc[n2][k1];
    cpx v = cmul(mk(vv.x, vv.y), t);
    sc[n2][k1] = make_float2(v.x, v.y);
  }
  __syncthreads();
  fft64v<1>(&sc[g][0], 1, l);
  int b = row >> 7, c = row & 127;
  const float* xb = &x[((size_t)b*256 + c)*4096];
  float* ob = &out[((size_t)b*256 + c)*4096];
  for (int idx=tid; idx<4096; idx+=512){
    float2 v = sc[idx&63][idx>>6];
    ob[idx] = sqrtf(v.x*v.x + v.y*v.y) * (1.f/65536.f) + xb[idx];
  }
}

// ---------------- K7: gate bottleneck only -> g_tq (2 MB) ----------------
__global__ void __launch_bounds__(256) k_gate(const float* __restrict__ w1,
                                              const float* __restrict__ w1b,
                                              const float* __restrict__ bnws,
                                              const float* __restrict__ bnwb)
{
  __shared__ float s_w1[8*128];
  __shared__ float s_tb[8], s_ta[8];
  int tid = threadIdx.x;
  for (int idx=tid; idx<1024; idx+=256) s_w1[idx] = w1[idx];
  if (tid < 8){ float a = bnws[tid]; s_ta[tid] = a; s_tb[tid] = w1b[tid]*a + bnwb[tid]; }
  __syncthreads();

  int t = blockIdx.x*256 + tid;
  int b = t >> 12;
  int p = t & 4095;
  const float2* fp = &g_f[(size_t)b*128*4096 + p];

  float acc[8];
  #pragma unroll
  for (int q=0;q<8;q++) acc[q] = 0.f;
  for (int c=0;c<128;c++){
    float r = fp[(size_t)c*4096].x;
    #pragma unroll
    for (int q=0;q<8;q++) acc[q] = fmaf(s_w1[q*128 + c], r, acc[q]);
  }
  float* tq = &g_tq[(size_t)t * 8];
  #pragma unroll
  for (int q=0;q<8;q++) tq[q] = fmaxf(fmaf(acc[q], s_ta[q], s_tb[q]), 0.f);
}

// ---------------- K8: spatial ifft2 of (gate*f) + abs + residual ------------
// gate reconstructed from bottleneck: sigmoid(w2[c]·tq[b][p] + b2[c])
__global__ void __launch_bounds__(512) k_ifft2sp(const float* __restrict__ x,
                                                 const float* __restrict__ w2,
                                                 const float* __restrict__ w2b,
                                                 float* __restrict__ out){
  __shared__ float2 sc[64][FFT_PITCH];
  __shared__ float s_w2c[8];
  __shared__ float s_b2c;
  int bc = blockIdx.x;
  int b = bc >> 7, c = bc & 127;
  int tid = threadIdx.x;
  if (tid < 8) s_w2c[tid] = w2[c*8 + tid];
  if (tid == 8) s_b2c = w2b[c];
  __syncthreads();
  float w2r[8];
  #pragma unroll
  for (int q=0;q<8;q++) w2r[q] = s_w2c[q];
  float b2c = s_b2c;

  const float2* base = &g_f[(size_t)bc*4096];
  const float* tqb = &g_tq[(size_t)b*4096*8];
  for (int idx=tid; idx<4096; idx+=512){
    float s = b2c;
    const float* tq = tqb + (size_t)idx*8;
    #pragma unroll
    for (int q=0;q<8;q++) s = fmaf(w2r[q], tq[q], s);
    float gate = 1.f / (1.f + __expf(-s));
    float2 v = base[idx];
    sc[idx>>6][idx&63] = make_float2(v.x*gate, v.y*gate);
  }
  __syncthreads();
  int g = tid>>3, l = tid&7;
  fft64v<1>(&sc[0][g], FFT_PITCH, l);
  fft64v<1>(&sc[g][0], 1,         l);
  const float* xb = &x[((size_t)b*256 + 128 + c)*4096];
  float* ob = &out[((size_t)b*256 + 128 + c)*4096];
  for (int idx=tid; idx<4096; idx+=512){
    float2 v = sc[idx>>6][idx&63];
    ob[idx] = sqrtf(v.x*v.x + v.y*v.y) * (1.f/4096.f) + xb[idx];
  }
}

// ---------------- launch (single stream, serial) ----------------
extern "C" void kernel_launch(void* const* d_in, const int* in_sizes, int n_in,
                              void* d_out, int out_size) {
  (void)in_sizes; (void)n_in; (void)out_size;
  const float* x     = (const float*)d_in[0];
  const float* c2w   = (const float*)d_in[1];
  const float* c2b   = (const float*)d_in[2];
  const float* bn2s  = (const float*)d_in[3];
  const float* bn2b  = (const float*)d_in[4];
  const float* temp  = (const float*)d_in[5];
  const float* w1w   = (const float*)d_in[6];
  const float* w1b   = (const float*)d_in[7];
  const float* bnws  = (const float*)d_in[8];
  const float* bnwb  = (const float*)d_in[9];
  const float* w2w   = (const float*)d_in[10];
  const float* w2b   = (const float*)d_in[11];
  float* out = (float*)d_out;

  const int SMEM_CONV = 3*32768;   // 96KB, 3-stage ring
  cudaFuncSetAttribute(k_conv_mma, cudaFuncAttributeMaxDynamicSharedMemorySize, SMEM_CONV);

  k_xprep<<<2048, 256>>>(x);
  k_wprep<<<576, 256>>>(c2w);
  k_conv_mma<<<512, 256, SMEM_CONV>>>(c2b, bn2s, bn2b);
  k_fft2<<<1024, 512>>>();
  k_gram_part<<<1024, 256>>>();
  k_gram_fin<<<128, 256>>>(temp);
  k_apply<<<1024, 256>>>();
  k_ifft4096<<<2048, 512>>>(x, out);
  k_gate<<<256, 256>>>(w1w, w1b, bnws, bnwb);
  k_ifft2sp<<<2048, 512>>>(x, w2w, w2b, out);
}

// round 16
// speedup vs baseline: 1.0266x; 1.0266x over previous
#include <cuda_runtime.h>
#include <cuda_fp16.h>
#include <math.h>
#include <stdint.h>

#define PI2F 6.28318530717958647692f

// ---------------- scratch (device globals; no allocation) ----------------
static __device__ float  g_conv[16*128*4096];      // conv2+BN+ReLU output
static __device__ float2 g_f   [16*128*4096];      // fft2 spectrum
static __device__ float  g_norm[16*128];           // per-(b,c) spectral L2 norm
static __device__ float2 g_attn[16*8*256];         // softmaxed attention (b,h,16,16)
static __device__ float2 g_outf[16*128*4096];      // cp-IDFT'd spectrum
static __device__ uint32_t g_xh[16*4096*128];      // X fp16 pairs, pixel-major: [b][hw][icp]
static __device__ uint32_t g_wsplit[36*4096];      // weight chunks fp16, pre-swizzled
static __device__ float2 g_gpart[8*128*256];       // partial gram sums [seg][bh][256]

// 16-pt inverse twiddles e^{+2*pi*i*t/16}
__constant__ float2 c_tw16[16] = {
  { 1.00000000f,  0.00000000f}, { 0.92387953f,  0.38268343f},
  { 0.70710678f,  0.70710678f}, { 0.38268343f,  0.92387953f},
  { 0.00000000f,  1.00000000f}, {-0.38268343f,  0.92387953f},
  {-0.70710678f,  0.70710678f}, {-0.92387953f,  0.38268343f},
  {-1.00000000f,  0.00000000f}, {-0.92387953f, -0.38268343f},
  {-0.70710678f, -0.70710678f}, {-0.38268343f, -0.92387953f},
  { 0.00000000f, -1.00000000f}, { 0.38268343f, -0.92387953f},
  { 0.70710678f, -0.70710678f}, { 0.92387953f, -0.38268343f}
};

// ================= helpers =================
__device__ __forceinline__ uint32_t smem_u32(const void* p){
  uint32_t a;
  asm("{ .reg .u64 t; cvta.to.shared.u64 t, %1; cvt.u32.u64 %0, t; }" : "=r"(a) : "l"(p));
  return a;
}
__device__ __forceinline__ uint32_t pack_h2(float v0, float v1){
  __half a0 = __float2half_rn(v0), a1 = __float2half_rn(v1);
  return (uint32_t)__half_as_ushort(a0) | ((uint32_t)__half_as_ushort(a1) << 16);
}
__device__ __forceinline__ void ldmx4(uint32_t* d, uint32_t addr){
  asm volatile("ldmatrix.sync.aligned.m8n8.x4.shared.b16 {%0,%1,%2,%3}, [%4];"
               : "=r"(d[0]), "=r"(d[1]), "=r"(d[2]), "=r"(d[3]) : "r"(addr));
}
__device__ __forceinline__ void mma16816h(float* d, const uint32_t* a, const uint32_t* b){
  asm volatile(
    "mma.sync.aligned.m16n8k16.row.col.f32.f16.f16.f32 "
    "{%0,%1,%2,%3}, {%4,%5,%6,%7}, {%8,%9}, {%0,%1,%2,%3};"
    : "+f"(d[0]), "+f"(d[1]), "+f"(d[2]), "+f"(d[3])
    : "r"(a[0]), "r"(a[1]), "r"(a[2]), "r"(a[3]), "r"(b[0]), "r"(b[1]));
}
__device__ __forceinline__ void cp16(uint32_t dst, const void* src, uint32_t sz){
  asm volatile("cp.async.cg.shared.global [%0], [%1], 16, %2;"
               :: "r"(dst), "l"(src), "r"(sz) : "memory");
}

// ---------------- K0a: pack X to fp16 pairs, pixel-major transpose ----------
__global__ void __launch_bounds__(256) k_xprep(const float* __restrict__ X){
  __shared__ float st[256][33];
  int b   = blockIdx.x >> 7;
  int hw0 = (blockIdx.x & 127) * 32;
  int tid = threadIdx.x;
  #pragma unroll 8
  for (int it = 0; it < 32; ++it){
    int idx = it*256 + tid;
    int ch = idx >> 5, w = idx & 31;
    st[ch][w] = X[((size_t)b*256 + ch)*4096 + hw0 + w];
  }
  __syncthreads();
  #pragma unroll 4
  for (int it = 0; it < 16; ++it){
    int idx = it*256 + tid;
    int w = idx >> 7, icp = idx & 127;
    g_xh[((size_t)b*4096 + hw0 + w)*128 + icp] = pack_h2(st[2*icp][w], st[2*icp + 1][w]);
  }
}

// ---------------- K0b: pack + pre-swizzle weights per chunk ----------------
__global__ void __launch_bounds__(256) k_wprep(const float* __restrict__ W){
  int idx = blockIdx.x*256 + threadIdx.x;     // 36*4096 = 147456
  int chunk = idx >> 12;
  int rem = idx & 4095;
  int oc = rem >> 5, icp = rem & 31;
  int tap = chunk >> 2, icb = (chunk & 3) << 6;
  int ic = icb + 2*icp;
  float v0 = W[(size_t)(oc*256 + ic)*9 + tap];
  float v1 = W[(size_t)(oc*256 + ic + 1)*9 + tap];
  uint32_t off = ((uint32_t)(oc*128 + icp*4)) ^ (((uint32_t)(oc & 7)) << 4);
  g_wsplit[(chunk*16384u + off) >> 2] = pack_h2(v0, v1);
}

// ---------------- K1: conv as fp16 HMMA implicit GEMM, 3-stage ring ---------
// K-chunk = 128 ic (two 64-ic sub-tiles). Stage = 64KB:
//   A0 @0, A1 @16384, B0 @32768, B1 @49152. 18 chunks (2 per tap-half).
__global__ void __launch_bounds__(256) k_conv_mma(const float* __restrict__ cbp,
                                                  const float* __restrict__ bsc,
                                                  const float* __restrict__ bbi)
{
  extern __shared__ __align__(128) char sm[];
  __shared__ float s_prm[384];
  const int tid = threadIdx.x;
  const int wid = tid >> 5, lane = tid & 31;
  const int wm = wid & 3, wn = wid >> 2;
  const int b    = blockIdx.x >> 5;
  const int tile = blockIdx.x & 31;
  const int h0   = tile * 2;

  if (tid < 128){
    s_prm[tid]       = cbp[tid];
    s_prm[128 + tid] = bsc[tid];
    s_prm[256 + tid] = bbi[tid];
  }
  const uint32_t smb = smem_u32(sm);
  const int m = lane >> 3, r = lane & 7;
  const int fseg = tid & 7, fpr = tid >> 3;

  int rowA[2], xrA[2];
  #pragma unroll
  for (int mt=0; mt<2; ++mt){
    rowA[mt] = wm*32 + mt*16 + (m & 1)*8 + r;
    xrA[mt]  = (rowA[mt] & 7) << 4;
  }
  const int colAhalf = (m >> 1) * 16;
  int rowB[4], xrB[4];
  #pragma unroll
  for (int ntp=0; ntp<4; ++ntp){
    rowB[ntp] = wn*64 + ntp*16 + (m >> 1)*8 + r;
    xrB[ntp]  = (rowB[ntp] & 7) << 4;
  }
  const int colBhalf = (m & 1) * 16;

  float acc[2][8][4];
  #pragma unroll
  for (int i=0;i<2;i++)
    #pragma unroll
    for (int j=0;j<8;j++)
      #pragma unroll
      for (int q=0;q<4;q++) acc[i][j][q] = 0.f;

  // chunk n (0..17): tap = n>>1, ic-groups 2*(n&1) and 2*(n&1)+1
  auto fill = [&](int n, uint32_t sb){
    const int tap = n >> 1;
    const int dy = (tap / 3) * 3 - 3, dx = (tap % 3) * 3 - 3;
    #pragma unroll
    for (int icg = 0; icg < 2; ++icg){
      const int grp = (n & 1) * 2 + icg;       // 0..3
      const int icpg0 = grp << 5;
      const uint32_t abase = sb + (uint32_t)icg * 16384u;
      #pragma unroll
      for (int it = 0; it < 4; ++it){
        int px = it*32 + fpr;
        int hh = h0 + (px >> 6) + dy;
        int ww = (px & 63) + dx;
        bool valid = ((unsigned)hh < 64u) && ((unsigned)ww < 64u);
        size_t gbase = (((size_t)b*4096) + (valid ? hh*64 + ww : 0))*128 + icpg0;
        uint32_t sz = valid ? 16u : 0u;
        uint32_t off = (uint32_t)(px*128) + (((uint32_t)(fseg*16)) ^ (((uint32_t)(px & 7)) << 4));
        cp16(smb + abase + off, (const char*)(g_xh + gbase) + fseg*16, sz);
      }
      const uint4* wsrc = (const uint4*)&g_wsplit[(tap*4 + grp) * 4096];
      const uint32_t bbase = sb + 32768u + (uint32_t)icg * 16384u;
      #pragma unroll
      for (int it = 0; it < 4; ++it){
        int idx = it*256 + tid;
        cp16(smb + bbase + idx*16, wsrc + idx, 16);
      }
    }
    asm volatile("cp.async.commit_group;" ::: "memory");
  };

  // 3-stage ring: stages at 0, 65536, 131072
  fill(0, 0);
  fill(1, 65536);
  for (int n = 0; n < 18; ++n){
    const uint32_t sb = (uint32_t)(n % 3) * 65536u;
    if (n < 17){
      asm volatile("cp.async.wait_group 1;" ::: "memory");
    } else {
      asm volatile("cp.async.wait_group 0;" ::: "memory");
    }
    __syncthreads();

    #pragma unroll
    for (int icg = 0; icg < 2; ++icg){
      const uint32_t abase = smb + sb + (uint32_t)icg * 16384u;
      const uint32_t bbase = smb + sb + 32768u + (uint32_t)icg * 16384u;
      #pragma unroll
      for (int kk = 0; kk < 4; ++kk){
        uint32_t ah[2][4];
        const int colA = kk*32 + colAhalf;
        #pragma unroll
        for (int mt=0; mt<2; ++mt){
          uint32_t aaddr = abase + rowA[mt]*128 + (colA ^ xrA[mt]);
          ldmx4(ah[mt], aaddr);
        }
        const int colB = kk*32 + colBhalf;
        #pragma unroll
        for (int ntp=0; ntp<4; ++ntp){
          uint32_t bh[4];
          uint32_t baddr = bbase + rowB[ntp]*128 + (colB ^ xrB[ntp]);
          ldmx4(bh, baddr);
          #pragma unroll
          for (int mt=0; mt<2; ++mt){
            #pragma unroll
            for (int hf=0; hf<2; ++hf)
              mma16816h(acc[mt][ntp*2 + hf], ah[mt], bh + hf*2);
          }
        }
      }
    }
    if (n + 2 <= 17)
      fill(n + 2, (uint32_t)((n + 2) % 3) * 65536u);
  }

  const int g2 = lane >> 2, tig = lane & 3;
  float* outb = &g_conv[(size_t)b*128*4096 + h0*64];
  #pragma unroll
  for (int mt=0; mt<2; ++mt){
    int px0 = wm*32 + mt*16 + g2;
    #pragma unroll
    for (int nt=0; nt<8; ++nt){
      int oc0 = wn*64 + nt*8 + 2*tig;
      #pragma unroll
      for (int q=0; q<4; ++q){
        int px = px0 + (q >> 1)*8;
        int oc = oc0 + (q & 1);
        float v = (acc[mt][nt][q] + s_prm[oc]) * s_prm[128+oc] + s_prm[256+oc];
        outb[(size_t)oc*4096 + px] = fmaxf(v, 0.f);
      }
    }
  }
}

// ---------------- complex helpers ----------------
struct cpx { float x, y; };
__device__ __forceinline__ cpx mk(float a, float b){ cpx r; r.x=a; r.y=b; return r; }
__device__ __forceinline__ cpx cadd(cpx a, cpx b){ return mk(a.x+b.x, a.y+b.y); }
__device__ __forceinline__ cpx csub(cpx a, cpx b){ return mk(a.x-b.x, a.y-b.y); }
__device__ __forceinline__ cpx cmul(cpx a, cpx b){ return mk(a.x*b.x - a.y*b.y, a.x*b.y + a.y*b.x); }

template<int S>
__device__ __forceinline__ cpx mulJ(cpx a){
  return (S < 0) ? mk(a.y, -a.x) : mk(-a.y, a.x);
}
template<int S>
__device__ __forceinline__ cpx tw(int t, int N){
  t &= (N - 1);
  if (t > (N >> 1)) t -= N;
  float a = ((S < 0) ? -PI2F : PI2F) * (float)t / (float)N;
  float s, c;
  __sincosf(a, &s, &c);
  return mk(c, s);
}
template<int S>
__device__ __forceinline__ void dft8(cpx v[8]){
  const float r = 0.70710678118654752440f;
  cpx a0=cadd(v[0],v[4]), a1=csub(v[0],v[4]);
  cpx a2=cadd(v[2],v[6]), a3=csub(v[2],v[6]);
  cpx a4=cadd(v[1],v[5]), a5=csub(v[1],v[5]);
  cpx a6=cadd(v[3],v[7]), a7=csub(v[3],v[7]);
  cpx j3 = mulJ<S>(a3);
  cpx E0=cadd(a0,a2), E2=csub(a0,a2), E1=cadd(a1,j3), E3=csub(a1,j3);
  cpx j7 = mulJ<S>(a7);
  cpx O0=cadd(a4,a6), O2=csub(a4,a6), O1=cadd(a5,j7), O3=csub(a5,j7);
  cpx w1 = mk(r, (S<0)? -r : r);
  cpx w3 = mk(-r, (S<0)? -r : r);
  cpx t1 = cmul(O1, w1);
  cpx t2 = mulJ<S>(O2);
  cpx t3 = cmul(O3, w3);
  v[0]=cadd(E0,O0); v[4]=csub(E0,O0);
  v[1]=cadd(E1,t1); v[5]=csub(E1,t1);
  v[2]=cadd(E2,t2); v[6]=csub(E2,t2);
  v[3]=cadd(E3,t3); v[7]=csub(E3,t3);
}
// 64-pt DFT on float2 smem; elements at base[i*stride]; 8-thread group (lane l)
template<int S>
__device__ void fft64v(float2* base, int stride, int l){
  cpx v[8];
  #pragma unroll
  for (int j=0;j<8;j++){ float2 t = base[(l+8*j)*stride]; v[j]=mk(t.x, t.y); }
  dft8<S>(v);
  #pragma unroll
  for (int k=1;k<8;k++) v[k] = cmul(v[k], tw<S>(l*k, 64));
  __syncwarp();
  #pragma unroll
  for (int k=0;k<8;k++) base[(l*8+k)*stride] = make_float2(v[k].x, v[k].y);
  __syncwarp();
  #pragma unroll
  for (int j=0;j<8;j++){ float2 t = base[(j*8+l)*stride]; v[j]=mk(t.x, t.y); }
  dft8<S>(v);
  #pragma unroll
  for (int k=0;k<8;k++) base[(k*8+l)*stride] = make_float2(v[k].x, v[k].y);
  __syncthreads();
}

#define FFT_PITCH 66

// ---------------- K2: packed 2-channel forward fft2 + norms ----------------
__global__ void __launch_bounds__(512) k_fft2(){
  __shared__ float2 sc[64][FFT_PITCH];
  __shared__ float s_sum0, s_sum1;
  int bc2 = blockIdx.x;
  int tid = threadIdx.x;
  if (tid==0){ s_sum0 = 0.f; s_sum1 = 0.f; }
  const float* src0 = &g_conv[(size_t)(2*bc2)*4096];
  const float* src1 = src0 + 4096;
  for (int idx=tid; idx<4096; idx+=512)
    sc[idx>>6][idx&63] = make_float2(src0[idx], src1[idx]);
  __syncthreads();
  int g = tid>>3, l = tid&7;
  fft64v<-1>(&sc[0][g], FFT_PITCH, l);
  fft64v<-1>(&sc[g][0], 1,         l);
  float p0 = 0.f, p1 = 0.f;
  float2* f0 = &g_f[(size_t)(2*bc2)*4096];
  float2* f1 = f0 + 4096;
  for (int idx=tid; idx<4096; idx+=512){
    int kh = idx>>6, kw = idx&63;
    float2 Z  = sc[kh][kw];
    float2 Zm = sc[(64-kh)&63][(64-kw)&63];
    float2 F0 = make_float2(0.5f*(Z.x + Zm.x), 0.5f*(Z.y - Zm.y));
    float2 F1 = make_float2(0.5f*(Z.y + Zm.y), 0.5f*(Zm.x - Z.x));
    f0[idx] = F0; f1[idx] = F1;
    p0 = fmaf(F0.x, F0.x, p0); p0 = fmaf(F0.y, F0.y, p0);
    p1 = fmaf(F1.x, F1.x, p1); p1 = fmaf(F1.y, F1.y, p1);
  }
  #pragma unroll
  for (int s=16;s;s>>=1){
    p0 += __shfl_xor_sync(0xffffffffu, p0, s);
    p1 += __shfl_xor_sync(0xffffffffu, p1, s);
  }
  if ((tid&31)==0){ atomicAdd(&s_sum0, p0); atomicAdd(&s_sum1, p1); }
  __syncthreads();
  if (tid==0){
    g_norm[2*bc2]   = sqrtf(s_sum0);
    g_norm[2*bc2+1] = sqrtf(s_sum1);
  }
}

// ---------------- K3a: partial gram sums ----------
__global__ void __launch_bounds__(256) k_gram_part(){
  __shared__ float2 sQ[16][129];
  int bh  = blockIdx.x >> 3;
  int seg = blockIdx.x & 7;
  int tid = threadIdx.x;
  int i = tid >> 4, jj = tid & 15;
  float ax=0.f, ay=0.f;
  int ch0 = seg * 512;
  for (int ch = ch0; ch < ch0 + 512; ch += 128){
    for (int idx=tid; idx<2048; idx+=256)
      sQ[idx>>7][idx&127] = g_f[(bh*16 + (idx>>7))*4096 + ch + (idx&127)];
    __syncthreads();
    #pragma unroll 4
    for (int n=0;n<128;n++){
      float2 a = sQ[i][n], b = sQ[jj][n];
      ax = fmaf(a.x, b.x, ax); ax = fmaf(-a.y, b.y, ax);
      ay = fmaf(a.x, b.y, ay); ay = fmaf(a.y, b.x, ay);
    }
    __syncthreads();
  }
  g_gpart[(seg*128 + bh)*256 + tid] = make_float2(ax, ay);
}

// ---------------- K3b: reduce partials + normalize + dual softmax -----------
__global__ void __launch_bounds__(256) k_gram_fin(const float* __restrict__ temp){
  int bh = blockIdx.x;
  int tid = threadIdx.x;
  int i = tid >> 4, jj = tid & 15;
  float ax=0.f, ay=0.f;
  #pragma unroll
  for (int s=0;s<8;s++){
    float2 p = g_gpart[(s*128 + bh)*256 + tid];
    ax += p.x; ay += p.y;
  }
  float ni = fmaxf(g_norm[bh*16 + i],  1e-12f);
  float nj = fmaxf(g_norm[bh*16 + jj], 1e-12f);
  float sc = temp[bh & 7] / (ni*nj);
  float gr = ax*sc, gi = ay*sc;
  float mr = gr, mi = gi;
  #pragma unroll
  for (int m2=8;m2;m2>>=1){
    mr = fmaxf(mr, __shfl_xor_sync(0xffffffffu, mr, m2));
    mi = fmaxf(mi, __shfl_xor_sync(0xffffffffu, mi, m2));
  }
  float er = __expf(gr - mr), ei = __expf(gi - mi);
  float srn = er, sin_ = ei;
  #pragma unroll
  for (int m2=8;m2;m2>>=1){
    srn  += __shfl_xor_sync(0xffffffffu, srn, m2);
    sin_ += __shfl_xor_sync(0xffffffffu, sin_, m2);
  }
  g_attn[bh*256 + tid] = make_float2(er/srn, ei/sin_);
}

// ---------------- K4: apply attention + in-register 16-pt cp-IDFT ----------
__global__ void __launch_bounds__(256) k_apply(){
  __shared__ float2 sF[16][257];
  __shared__ float2 sA[256];
  int bh = blockIdx.x >> 3;
  int cq = blockIdx.x & 7;
  int tid = threadIdx.x;
  sA[tid] = g_attn[bh*256 + tid];
  int ch0 = cq * 512;
  for (int ch=ch0; ch<ch0+512; ch+=256){
    #pragma unroll
    for (int k=0;k<16;k++){
      int idx = tid + k*256;
      sF[idx>>8][idx&255] = g_f[(bh*16 + (idx>>8))*4096 + ch + (idx&255)];
    }
    __syncthreads();
    float2 acc[16];
    #pragma unroll
    for (int i=0;i<16;i++) acc[i] = make_float2(0.f, 0.f);
    #pragma unroll
    for (int j=0;j<16;j++){
      float2 fv = sF[j][tid];
      #pragma unroll
      for (int i=0;i<16;i++){
        float2 a = sA[i*16 + j];
        acc[i].x = fmaf(a.x, fv.x, acc[i].x); acc[i].x = fmaf(-a.y, fv.y, acc[i].x);
        acc[i].y = fmaf(a.x, fv.y, acc[i].y); acc[i].y = fmaf(a.y, fv.x, acc[i].y);
      }
    }
    float2 inner[4][4];
    #pragma unroll
    for (int j=0;j<4;j++){
      float2 x0 = acc[j], x1 = acc[j+4], x2 = acc[j+8], x3 = acc[j+12];
      float t0x = x0.x + x2.x, t0y = x0.y + x2.y;
      float t1x = x0.x - x2.x, t1y = x0.y - x2.y;
      float t2x = x1.x + x3.x, t2y = x1.y + x3.y;
      float t3x = -(x1.y - x3.y), t3y = x1.x - x3.x;
      inner[j][0] = make_float2(t0x + t2x, t0y + t2y);
      inner[j][1] = make_float2(t1x + t3x, t1y + t3y);
      inner[j][2] = make_float2(t0x - t2x, t0y - t2y);
      inner[j][3] = make_float2(t1x - t3x, t1y - t3y);
    }
    #pragma unroll
    for (int ip=0; ip<16; ip++){
      int p = ip & 3;
      float2 y = inner[0][p];
      #pragma unroll
      for (int j=1;j<4;j++){
        float2 w = c_tw16[(ip*j) & 15];
        float2 v = inner[j][p];
        y.x = fmaf(v.x, w.x, y.x); y.x = fmaf(-v.y, w.y, y.x);
        y.y = fmaf(v.x, w.y, y.y); y.y = fmaf( v.y, w.x, y.y);
      }
      g_outf[(bh*16 + ip)*4096 + ch + tid] = y;
    }
    __syncthreads();
  }
}

// ---------------- K5: 4096-pt IFFT per row + abs + residual -> out ----------
__global__ void __launch_bounds__(512) k_ifft4096(const float* __restrict__ x,
                                                  float* __restrict__ out){
  __shared__ float2 sc[64][FFT_PITCH];
  int row = blockIdx.x;
  int tid = threadIdx.x;
  const float2* base = &g_outf[(size_t)row*4096];
  for (int idx=tid; idx<4096; idx+=512)
    sc[idx>>6][idx&63] = base[idx];
  __syncthreads();
  int g = tid>>3, l = tid&7;
  fft64v<1>(&sc[0][g], FFT_PITCH, l);
  for (int idx=tid; idx<4096; idx+=512){
    int n2 = idx>>6, k1 = idx&63;
    cpx t = tw<1>(n2*k1, 4096);
    float2 vv = sc[n2][k1];
    cpx v = cmul(mk(vv.x, vv.y), t);
    sc[n2][k1] = make_float2(v.x, v.y);
  }
  __syncthreads();
  fft64v<1>(&sc[g][0], 1, l);
  int b = row >> 7, c = row & 127;
  const float* xb = &x[((size_t)b*256 + c)*4096];
  float* ob = &out[((size_t)b*256 + c)*4096];
  for (int idx=tid; idx<4096; idx+=512){
    float2 v = sc[idx&63][idx>>6];
    ob[idx] = sqrtf(v.x*v.x + v.y*v.y) * (1.f/65536.f) + xb[idx];
  }
}

// ---------------- K7: gating MLP, scales g_f in place ----------------
__global__ void __launch_bounds__(256) k_gate(const float* __restrict__ w1,
                                              const float* __restrict__ w1b,
                                              const float* __restrict__ bnws,
                                              const float* __restrict__ bnwb,
                                              const float* __restrict__ w2,
                                              const float* __restrict__ w2b)
{
  __shared__ float s_w1[8*128];
  __shared__ float s_w2[128*8];
  __shared__ float s_tb[8], s_ta[8];
  __shared__ float s_b2[128];
  int tid = threadIdx.x;
  for (int idx=tid; idx<1024; idx+=256){ s_w1[idx] = w1[idx]; s_w2[idx] = w2[idx]; }
  if (tid < 8){ float a = bnws[tid]; s_ta[tid] = a; s_tb[tid] = w1b[tid]*a + bnwb[tid]; }
  if (tid < 128) s_b2[tid] = w2b[tid];
  __syncthreads();

  int t = blockIdx.x*256 + tid;
  int b = t >> 12;
  int p = t & 4095;
  float2* fp = &g_f[(size_t)b*128*4096 + p];

  float acc[8];
  #pragma unroll
  for (int q=0;q<8;q++) acc[q] = 0.f;
  for (int c=0;c<128;c++){
    float r = fp[(size_t)c*4096].x;
    #pragma unroll
    for (int q=0;q<8;q++) acc[q] = fmaf(s_w1[q*128 + c], r, acc[q]);
  }
  float tq[8];
  #pragma unroll
  for (int q=0;q<8;q++) tq[q] = fmaxf(fmaf(acc[q], s_ta[q], s_tb[q]), 0.f);

  for (int c=0;c<128;c++){
    float s = s_b2[c];
    #pragma unroll
    for (int q=0;q<8;q++) s = fmaf(s_w2[c*8 + q], tq[q], s);
    float gate = 1.f / (1.f + __expf(-s));
    float2 fv = fp[(size_t)c*4096];
    fp[(size_t)c*4096] = make_float2(fv.x*gate, fv.y*gate);
  }
}

// ---------------- K8: spatial inverse fft2 of g*f + abs + residual ----------
__global__ void __launch_bounds__(512) k_ifft2sp(const float* __restrict__ x,
                                                 float* __restrict__ out){
  __shared__ float2 sc[64][FFT_PITCH];
  int bc = blockIdx.x;
  int tid = threadIdx.x;
  const float2* base = &g_f[(size_t)bc*4096];
  for (int idx=tid; idx<4096; idx+=512)
    sc[idx>>6][idx&63] = base[idx];
  __syncthreads();
  int g = tid>>3, l = tid&7;
  fft64v<1>(&sc[0][g], FFT_PITCH, l);
  fft64v<1>(&sc[g][0], 1,         l);
  int b = bc >> 7, c = bc & 127;
  const float* xb = &x[((size_t)b*256 + 128 + c)*4096];
  float* ob = &out[((size_t)b*256 + 128 + c)*4096];
  for (int idx=tid; idx<4096; idx+=512){
    float2 v = sc[idx>>6][idx&63];
    ob[idx] = sqrtf(v.x*v.x + v.y*v.y) * (1.f/4096.f) + xb[idx];
  }
}

// ---------------- launch (single stream, serial) ----------------
extern "C" void kernel_launch(void* const* d_in, const int* in_sizes, int n_in,
                              void* d_out, int out_size) {
  (void)in_sizes; (void)n_in; (void)out_size;
  const float* x     = (const float*)d_in[0];
  const float* c2w   = (const float*)d_in[1];
  const float* c2b   = (const float*)d_in[2];
  const float* bn2s  = (const float*)d_in[3];
  const float* bn2b  = (const float*)d_in[4];
  const float* temp  = (const float*)d_in[5];
  const float* w1w   = (const float*)d_in[6];
  const float* w1b   = (const float*)d_in[7];
  const float* bnws  = (const float*)d_in[8];
  const float* bnwb  = (const float*)d_in[9];
  const float* w2w   = (const float*)d_in[10];
  const float* w2b   = (const float*)d_in[11];
  float* out = (float*)d_out;

  const int SMEM_CONV = 3*65536;   // 192KB, 3-stage ring (64KB stages)
  cudaFuncSetAttribute(k_conv_mma, cudaFuncAttributeMaxDynamicSharedMemorySize, SMEM_CONV);

  k_xprep<<<2048, 256>>>(x);
  k_wprep<<<576, 256>>>(c2w);
  k_conv_mma<<<512, 256, SMEM_CONV>>>(c2b, bn2s, bn2b);
  k_fft2<<<1024, 512>>>();
  k_gram_part<<<1024, 256>>>();
  k_gram_fin<<<128, 256>>>(temp);
  k_apply<<<1024, 256>>>();
  k_ifft4096<<<2048, 512>>>(x, out);
  k_gate<<<256, 256>>>(w1w, w1b, bnws, bnwb, w2w, w2b);
  k_ifft2sp<<<2048, 512>>>(x, out);
}

// round 17
// speedup vs baseline: 1.0370x; 1.0102x over previous
#include <cuda_runtime.h>
#include <cuda_fp16.h>
#include <math.h>
#include <stdint.h>

#define PI2F 6.28318530717958647692f

// ---------------- scratch (device globals; no allocation) ----------------
static __device__ float  g_conv[16*128*4096];      // conv2+BN+ReLU output
static __device__ float2 g_f   [16*128*4096];      // fft2 spectrum
static __device__ float  g_norm[16*128];           // per-(b,c) spectral L2 norm
static __device__ float2 g_attn[16*8*256];         // softmaxed attention (b,h,16,16)
static __device__ float2 g_outf[16*128*4096];      // cp-IDFT'd spectrum
static __device__ uint32_t g_xh[16*4096*128];      // X fp16 pairs, pixel-major: [b][hw][icp]
static __device__ uint32_t g_wsplit[36*4096];      // weight chunks fp16, pre-swizzled
static __device__ float2 g_gpart[8*128*256];       // partial gram sums [seg][bh][256]

// 16-pt inverse twiddles e^{+2*pi*i*t/16}
__constant__ float2 c_tw16[16] = {
  { 1.00000000f,  0.00000000f}, { 0.92387953f,  0.38268343f},
  { 0.70710678f,  0.70710678f}, { 0.38268343f,  0.92387953f},
  { 0.00000000f,  1.00000000f}, {-0.38268343f,  0.92387953f},
  {-0.70710678f,  0.70710678f}, {-0.92387953f,  0.38268343f},
  {-1.00000000f,  0.00000000f}, {-0.92387953f, -0.38268343f},
  {-0.70710678f, -0.70710678f}, {-0.38268343f, -0.92387953f},
  { 0.00000000f, -1.00000000f}, { 0.38268343f, -0.92387953f},
  { 0.70710678f, -0.70710678f}, { 0.92387953f, -0.38268343f}
};

// ================= helpers =================
__device__ __forceinline__ uint32_t smem_u32(const void* p){
  uint32_t a;
  asm("{ .reg .u64 t; cvta.to.shared.u64 t, %1; cvt.u32.u64 %0, t; }" : "=r"(a) : "l"(p));
  return a;
}
__device__ __forceinline__ uint32_t pack_h2(float v0, float v1){
  __half a0 = __float2half_rn(v0), a1 = __float2half_rn(v1);
  return (uint32_t)__half_as_ushort(a0) | ((uint32_t)__half_as_ushort(a1) << 16);
}
__device__ __forceinline__ void ldmx4(uint32_t* d, uint32_t addr){
  asm volatile("ldmatrix.sync.aligned.m8n8.x4.shared.b16 {%0,%1,%2,%3}, [%4];"
               : "=r"(d[0]), "=r"(d[1]), "=r"(d[2]), "=r"(d[3]) : "r"(addr));
}
__device__ __forceinline__ void mma16816h(float* d, const uint32_t* a, const uint32_t* b){
  asm volatile(
    "mma.sync.aligned.m16n8k16.row.col.f32.f16.f16.f32 "
    "{%0,%1,%2,%3}, {%4,%5,%6,%7}, {%8,%9}, {%0,%1,%2,%3};"
    : "+f"(d[0]), "+f"(d[1]), "+f"(d[2]), "+f"(d[3])
    : "r"(a[0]), "r"(a[1]), "r"(a[2]), "r"(a[3]), "r"(b[0]), "r"(b[1]));
}
__device__ __forceinline__ void cp16(uint32_t dst, const void* src, uint32_t sz){
  asm volatile("cp.async.cg.shared.global [%0], [%1], 16, %2;"
               :: "r"(dst), "l"(src), "r"(sz) : "memory");
}

// ---------------- K0a: pack X to fp16 pairs, pixel-major transpose ----------
__global__ void __launch_bounds__(256) k_xprep(const float* __restrict__ X){
  __shared__ float st[256][33];
  int b   = blockIdx.x >> 7;
  int hw0 = (blockIdx.x & 127) * 32;
  int tid = threadIdx.x;
  #pragma unroll 8
  for (int it = 0; it < 32; ++it){
    int idx = it*256 + tid;
    int ch = idx >> 5, w = idx & 31;
    st[ch][w] = X[((size_t)b*256 + ch)*4096 + hw0 + w];
  }
  __syncthreads();
  #pragma unroll 4
  for (int it = 0; it < 16; ++it){
    int idx = it*256 + tid;
    int w = idx >> 7, icp = idx & 127;
    g_xh[((size_t)b*4096 + hw0 + w)*128 + icp] = pack_h2(st[2*icp][w], st[2*icp + 1][w]);
  }
}

// ---------------- K0b: pack + pre-swizzle weights per chunk ----------------
__global__ void __launch_bounds__(256) k_wprep(const float* __restrict__ W){
  int idx = blockIdx.x*256 + threadIdx.x;     // 36*4096 = 147456
  int chunk = idx >> 12;
  int rem = idx & 4095;
  int oc = rem >> 5, icp = rem & 31;
  int tap = chunk >> 2, icb = (chunk & 3) << 6;
  int ic = icb + 2*icp;
  float v0 = W[(size_t)(oc*256 + ic)*9 + tap];
  float v1 = W[(size_t)(oc*256 + ic + 1)*9 + tap];
  uint32_t off = ((uint32_t)(oc*128 + icp*4)) ^ (((uint32_t)(oc & 7)) << 4);
  g_wsplit[(chunk*16384u + off) >> 2] = pack_h2(v0, v1);
}

// ---------------- K1: conv as fp16 HMMA implicit GEMM, 3-stage ring ---------
// Stage = 32KB: A fp16 tile [128px][64ic] @ +0, B fp16 tile [128oc][64ic] @ +16384
// Epilogue: stage output tile in smem (pitch 132) for coalesced stores.
__global__ void __launch_bounds__(256) k_conv_mma(const float* __restrict__ cbp,
                                                  const float* __restrict__ bsc,
                                                  const float* __restrict__ bbi)
{
  extern __shared__ __align__(128) char sm[];
  __shared__ float s_prm[384];
  const int tid = threadIdx.x;
  const int wid = tid >> 5, lane = tid & 31;
  const int wm = wid & 3, wn = wid >> 2;
  const int b    = blockIdx.x >> 5;
  const int tile = blockIdx.x & 31;
  const int h0   = tile * 2;

  if (tid < 128){
    s_prm[tid]       = cbp[tid];
    s_prm[128 + tid] = bsc[tid];
    s_prm[256 + tid] = bbi[tid];
  }
  const uint32_t smb = smem_u32(sm);
  const int m = lane >> 3, r = lane & 7;
  const int fseg = tid & 7, fpr = tid >> 3;

  int rowA[2], xrA[2];
  #pragma unroll
  for (int mt=0; mt<2; ++mt){
    rowA[mt] = wm*32 + mt*16 + (m & 1)*8 + r;
    xrA[mt]  = (rowA[mt] & 7) << 4;
  }
  const int colAhalf = (m >> 1) * 16;
  int rowB[4], xrB[4];
  #pragma unroll
  for (int ntp=0; ntp<4; ++ntp){
    rowB[ntp] = wn*64 + ntp*16 + (m >> 1)*8 + r;
    xrB[ntp]  = (rowB[ntp] & 7) << 4;
  }
  const int colBhalf = (m & 1) * 16;

  float acc[2][8][4];
  #pragma unroll
  for (int i=0;i<2;i++)
    #pragma unroll
    for (int j=0;j<8;j++)
      #pragma unroll
      for (int q=0;q<4;q++) acc[i][j][q] = 0.f;

  auto fill = [&](int n, uint32_t sb){
    const int tap = n >> 2;
    const int icpg0 = (n & 3) << 5;
    const int dy = (tap / 3) * 3 - 3, dx = (tap % 3) * 3 - 3;
    #pragma unroll
    for (int it = 0; it < 4; ++it){
      int px = it*32 + fpr;
      int hh = h0 + (px >> 6) + dy;
      int ww = (px & 63) + dx;
      bool valid = ((unsigned)hh < 64u) && ((unsigned)ww < 64u);
      size_t gbase = (((size_t)b*4096) + (valid ? hh*64 + ww : 0))*128 + icpg0;
      uint32_t sz = valid ? 16u : 0u;
      uint32_t off = (uint32_t)(px*128) + (((uint32_t)(fseg*16)) ^ (((uint32_t)(px & 7)) << 4));
      cp16(smb + sb + off, (const char*)(g_xh + gbase) + fseg*16, sz);
    }
    const uint4* wsrc = (const uint4*)&g_wsplit[n * 4096];
    #pragma unroll
    for (int it = 0; it < 4; ++it){
      int idx = it*256 + tid;
      cp16(smb + sb + 16384 + idx*16, wsrc + idx, 16);
    }
    asm volatile("cp.async.commit_group;" ::: "memory");
  };

  fill(0, 0);
  fill(1, 32768);
  for (int n = 0; n < 36; ++n){
    const uint32_t sb = (uint32_t)(n % 3) * 32768u;
    if (n < 35){
      asm volatile("cp.async.wait_group 1;" ::: "memory");
    } else {
      asm volatile("cp.async.wait_group 0;" ::: "memory");
    }
    __syncthreads();

    #pragma unroll
    for (int kk = 0; kk < 4; ++kk){
      uint32_t ah[2][4];
      const int colA = kk*32 + colAhalf;
      #pragma unroll
      for (int mt=0; mt<2; ++mt){
        uint32_t aaddr = smb + sb + rowA[mt]*128 + (colA ^ xrA[mt]);
        ldmx4(ah[mt], aaddr);
      }
      const int colB = kk*32 + colBhalf;
      #pragma unroll
      for (int ntp=0; ntp<4; ++ntp){
        uint32_t bh[4];
        uint32_t baddr = smb + sb + 16384 + rowB[ntp]*128 + (colB ^ xrB[ntp]);
        ldmx4(bh, baddr);
        #pragma unroll
        for (int mt=0; mt<2; ++mt){
          #pragma unroll
          for (int hf=0; hf<2; ++hf)
            mma16816h(acc[mt][ntp*2 + hf], ah[mt], bh + hf*2);
        }
      }
    }
    if (n + 2 <= 35)
      fill(n + 2, (uint32_t)((n + 2) % 3) * 32768u);
  }

  // ---- epilogue: stage tile in smem (pitch 132), coalesced global stores ---
  __syncthreads();                 // ring smem now dead; reuse as [128oc][132]
  float* stile = (float*)sm;
  const int g2 = lane >> 2, tig = lane & 3;
  #pragma unroll
  for (int mt=0; mt<2; ++mt){
    int px0 = wm*32 + mt*16 + g2;
    #pragma unroll
    for (int nt=0; nt<8; ++nt){
      int oc0 = wn*64 + nt*8 + 2*tig;
      #pragma unroll
      for (int q=0; q<4; ++q){
        int px = px0 + (q >> 1)*8;
        int oc = oc0 + (q & 1);
        stile[oc*132 + px] = acc[mt][nt][q];
      }
    }
  }
  __syncthreads();
  float* outb = &g_conv[(size_t)b*128*4096 + h0*64];
  #pragma unroll
  for (int it = 0; it < 64; ++it){
    int idx = it*256 + tid;
    int oc = idx >> 7, px = idx & 127;
    float v = (stile[oc*132 + px] + s_prm[oc]) * s_prm[128+oc] + s_prm[256+oc];
    outb[(size_t)oc*4096 + px] = fmaxf(v, 0.f);
  }
}

// ---------------- complex helpers ----------------
struct cpx { float x, y; };
__device__ __forceinline__ cpx mk(float a, float b){ cpx r; r.x=a; r.y=b; return r; }
__device__ __forceinline__ cpx cadd(cpx a, cpx b){ return mk(a.x+b.x, a.y+b.y); }
__device__ __forceinline__ cpx csub(cpx a, cpx b){ return mk(a.x-b.x, a.y-b.y); }
__device__ __forceinline__ cpx cmul(cpx a, cpx b){ return mk(a.x*b.x - a.y*b.y, a.x*b.y + a.y*b.x); }

template<int S>
__device__ __forceinline__ cpx mulJ(cpx a){
  return (S < 0) ? mk(a.y, -a.x) : mk(-a.y, a.x);
}
template<int S>
__device__ __forceinline__ cpx tw(int t, int N){
  t &= (N - 1);
  if (t > (N >> 1)) t -= N;
  float a = ((S < 0) ? -PI2F : PI2F) * (float)t / (float)N;
  float s, c;
  __sincosf(a, &s, &c);
  return mk(c, s);
}
template<int S>
__device__ __forceinline__ void dft8(cpx v[8]){
  const float r = 0.70710678118654752440f;
  cpx a0=cadd(v[0],v[4]), a1=csub(v[0],v[4]);
  cpx a2=cadd(v[2],v[6]), a3=csub(v[2],v[6]);
  cpx a4=cadd(v[1],v[5]), a5=csub(v[1],v[5]);
  cpx a6=cadd(v[3],v[7]), a7=csub(v[3],v[7]);
  cpx j3 = mulJ<S>(a3);
  cpx E0=cadd(a0,a2), E2=csub(a0,a2), E1=cadd(a1,j3), E3=csub(a1,j3);
  cpx j7 = mulJ<S>(a7);
  cpx O0=cadd(a4,a6), O2=csub(a4,a6), O1=cadd(a5,j7), O3=csub(a5,j7);
  cpx w1 = mk(r, (S<0)? -r : r);
  cpx w3 = mk(-r, (S<0)? -r : r);
  cpx t1 = cmul(O1, w1);
  cpx t2 = mulJ<S>(O2);
  cpx t3 = cmul(O3, w3);
  v[0]=cadd(E0,O0); v[4]=csub(E0,O0);
  v[1]=cadd(E1,t1); v[5]=csub(E1,t1);
  v[2]=cadd(E2,t2); v[6]=csub(E2,t2);
  v[3]=cadd(E3,t3); v[7]=csub(E3,t3);
}
// 64-pt DFT on float2 smem; elements at base[i*stride]; 8-thread group (lane l)
template<int S>
__device__ void fft64v(float2* base, int stride, int l){
  cpx v[8];
  #pragma unroll
  for (int j=0;j<8;j++){ float2 t = base[(l+8*j)*stride]; v[j]=mk(t.x, t.y); }
  dft8<S>(v);
  #pragma unroll
  for (int k=1;k<8;k++) v[k] = cmul(v[k], tw<S>(l*k, 64));
  __syncwarp();
  #pragma unroll
  for (int k=0;k<8;k++) base[(l*8+k)*stride] = make_float2(v[k].x, v[k].y);
  __syncwarp();
  #pragma unroll
  for (int j=0;j<8;j++){ float2 t = base[(j*8+l)*stride]; v[j]=mk(t.x, t.y); }
  dft8<S>(v);
  #pragma unroll
  for (int k=0;k<8;k++) base[(k*8+l)*stride] = make_float2(v[k].x, v[k].y);
  __syncthreads();
}

#define FFT_PITCH 66

// ---------------- K2: packed 2-channel forward fft2 + norms ----------------
__global__ void __launch_bounds__(512) k_fft2(){
  __shared__ float2 sc[64][FFT_PITCH];
  __shared__ float s_sum0, s_sum1;
  int bc2 = blockIdx.x;
  int tid = threadIdx.x;
  if (tid==0){ s_sum0 = 0.f; s_sum1 = 0.f; }
  const float* src0 = &g_conv[(size_t)(2*bc2)*4096];
  const float* src1 = src0 + 4096;
  for (int idx=tid; idx<4096; idx+=512)
    sc[idx>>6][idx&63] = make_float2(src0[idx], src1[idx]);
  __syncthreads();
  int g = tid>>3, l = tid&7;
  fft64v<-1>(&sc[0][g], FFT_PITCH, l);
  fft64v<-1>(&sc[g][0], 1,         l);
  float p0 = 0.f, p1 = 0.f;
  float2* f0 = &g_f[(size_t)(2*bc2)*4096];
  float2* f1 = f0 + 4096;
  for (int idx=tid; idx<4096; idx+=512){
    int kh = idx>>6, kw = idx&63;
    float2 Z  = sc[kh][kw];
    float2 Zm = sc[(64-kh)&63][(64-kw)&63];
    float2 F0 = make_float2(0.5f*(Z.x + Zm.x), 0.5f*(Z.y - Zm.y));
    float2 F1 = make_float2(0.5f*(Z.y + Zm.y), 0.5f*(Zm.x - Z.x));
    f0[idx] = F0; f1[idx] = F1;
    p0 = fmaf(F0.x, F0.x, p0); p0 = fmaf(F0.y, F0.y, p0);
    p1 = fmaf(F1.x, F1.x, p1); p1 = fmaf(F1.y, F1.y, p1);
  }
  #pragma unroll
  for (int s=16;s;s>>=1){
    p0 += __shfl_xor_sync(0xffffffffu, p0, s);
    p1 += __shfl_xor_sync(0xffffffffu, p1, s);
  }
  if ((tid&31)==0){ atomicAdd(&s_sum0, p0); atomicAdd(&s_sum1, p1); }
  __syncthreads();
  if (tid==0){
    g_norm[2*bc2]   = sqrtf(s_sum0);
    g_norm[2*bc2+1] = sqrtf(s_sum1);
  }
}

// ---------------- K3a: partial gram sums ----------
__global__ void __launch_bounds__(256) k_gram_part(){
  __shared__ float2 sQ[16][129];
  int bh  = blockIdx.x >> 3;
  int seg = blockIdx.x & 7;
  int tid = threadIdx.x;
  int i = tid >> 4, jj = tid & 15;
  float ax=0.f, ay=0.f;
  int ch0 = seg * 512;
  for (int ch = ch0; ch < ch0 + 512; ch += 128){
    for (int idx=tid; idx<2048; idx+=256)
      sQ[idx>>7][idx&127] = g_f[(bh*16 + (idx>>7))*4096 + ch + (idx&127)];
    __syncthreads();
    #pragma unroll 4
    for (int n=0;n<128;n++){
      float2 a = sQ[i][n], b = sQ[jj][n];
      ax = fmaf(a.x, b.x, ax); ax = fmaf(-a.y, b.y, ax);
      ay = fmaf(a.x, b.y, ay); ay = fmaf(a.y, b.x, ay);
    }
    __syncthreads();
  }
  g_gpart[(seg*128 + bh)*256 + tid] = make_float2(ax, ay);
}

// ---------------- K3b: reduce partials + normalize + dual softmax -----------
__global__ void __launch_bounds__(256) k_gram_fin(const float* __restrict__ temp){
  int bh = blockIdx.x;
  int tid = threadIdx.x;
  int i = tid >> 4, jj = tid & 15;
  float ax=0.f, ay=0.f;
  #pragma unroll
  for (int s=0;s<8;s++){
    float2 p = g_gpart[(s*128 + bh)*256 + tid];
    ax += p.x; ay += p.y;
  }
  float ni = fmaxf(g_norm[bh*16 + i],  1e-12f);
  float nj = fmaxf(g_norm[bh*16 + jj], 1e-12f);
  float sc = temp[bh & 7] / (ni*nj);
  float gr = ax*sc, gi = ay*sc;
  float mr = gr, mi = gi;
  #pragma unroll
  for (int m2=8;m2;m2>>=1){
    mr = fmaxf(mr, __shfl_xor_sync(0xffffffffu, mr, m2));
    mi = fmaxf(mi, __shfl_xor_sync(0xffffffffu, mi, m2));
  }
  float er = __expf(gr - mr), ei = __expf(gi - mi);
  float srn = er, sin_ = ei;
  #pragma unroll
  for (int m2=8;m2;m2>>=1){
    srn  += __shfl_xor_sync(0xffffffffu, srn, m2);
    sin_ += __shfl_xor_sync(0xffffffffu, sin_, m2);
  }
  g_attn[bh*256 + tid] = make_float2(er/srn, ei/sin_);
}

// ---------------- K4: apply attention + in-register 16-pt cp-IDFT ----------
__global__ void __launch_bounds__(256) k_apply(){
  __shared__ float2 sF[16][257];
  __shared__ float2 sA[256];
  int bh = blockIdx.x >> 3;
  int cq = blockIdx.x & 7;
  int tid = threadIdx.x;
  sA[tid] = g_attn[bh*256 + tid];
  int ch0 = cq * 512;
  for (int ch=ch0; ch<ch0+512; ch+=256){
    #pragma unroll
    for (int k=0;k<16;k++){
      int idx = tid + k*256;
      sF[idx>>8][idx&255] = g_f[(bh*16 + (idx>>8))*4096 + ch + (idx&255)];
    }
    __syncthreads();
    float2 acc[16];
    #pragma unroll
    for (int i=0;i<16;i++) acc[i] = make_float2(0.f, 0.f);
    #pragma unroll
    for (int j=0;j<16;j++){
      float2 fv = sF[j][tid];
      #pragma unroll
      for (int i=0;i<16;i++){
        float2 a = sA[i*16 + j];
        acc[i].x = fmaf(a.x, fv.x, acc[i].x); acc[i].x = fmaf(-a.y, fv.y, acc[i].x);
        acc[i].y = fmaf(a.x, fv.y, acc[i].y); acc[i].y = fmaf(a.y, fv.x, acc[i].y);
      }
    }
    float2 inner[4][4];
    #pragma unroll
    for (int j=0;j<4;j++){
      float2 x0 = acc[j], x1 = acc[j+4], x2 = acc[j+8], x3 = acc[j+12];
      float t0x = x0.x + x2.x, t0y = x0.y + x2.y;
      float t1x = x0.x - x2.x, t1y = x0.y - x2.y;
      float t2x = x1.x + x3.x, t2y = x1.y + x3.y;
      float t3x = -(x1.y - x3.y), t3y = x1.x - x3.x;
      inner[j][0] = make_float2(t0x + t2x, t0y + t2y);
      inner[j][1] = make_float2(t1x + t3x, t1y + t3y);
      inner[j][2] = make_float2(t0x - t2x, t0y - t2y);
      inner[j][3] = make_float2(t1x - t3x, t1y - t3y);
    }
    #pragma unroll
    for (int ip=0; ip<16; ip++){
      int p = ip & 3;
      float2 y = inner[0][p];
      #pragma unroll
      for (int j=1;j<4;j++){
        float2 w = c_tw16[(ip*j) & 15];
        float2 v = inner[j][p];
        y.x = fmaf(v.x, w.x, y.x); y.x = fmaf(-v.y, w.y, y.x);
        y.y = fmaf(v.x, w.y, y.y); y.y = fmaf( v.y, w.x, y.y);
      }
      g_outf[(bh*16 + ip)*4096 + ch + tid] = y;
    }
    __syncthreads();
  }
}

// ---------------- K5: 4096-pt IFFT per row + abs + residual -> out ----------
__global__ void __launch_bounds__(512) k_ifft4096(const float* __restrict__ x,
                                                  float* __restrict__ out){
  __shared__ float2 sc[64][FFT_PITCH];
  int row = blockIdx.x;
  int tid = threadIdx.x;
  const float2* base = &g_outf[(size_t)row*4096];
  for (int idx=tid; idx<4096; idx+=512)
    sc[idx>>6][idx&63] = base[idx];
  __syncthreads();
  int g = tid>>3, l = tid&7;
  fft64v<1>(&sc[0][g], FFT_PITCH, l);
  for (int idx=tid; idx<4096; idx+=512){
    int n2 = idx>>6, k1 = idx&63;
    cpx t = tw<1>(n2*k1, 4096);
    float2 vv = sc[n2][k1];
    cpx v = cmul(mk(vv.x, vv.y), t);
    sc[n2][k1] = make_float2(v.x, v.y);
  }
  __syncthreads();
  fft64v<1>(&sc[g][0], 1, l);
  int b = row >> 7, c = row & 127;
  const float* xb = &x[((size_t)b*256 + c)*4096];
  float* ob = &out[((size_t)b*256 + c)*4096];
  for (int idx=tid; idx<4096; idx+=512){
    float2 v = sc[idx&63][idx>>6];
    ob[idx] = sqrtf(v.x*v.x + v.y*v.y) * (1.f/65536.f) + xb[idx];
  }
}

// ---------------- K7: gating MLP, scales g_f in place ----------------
__global__ void __launch_bounds__(256) k_gate(const float* __restrict__ w1,
                                              const float* __restrict__ w1b,
                                              const float* __restrict__ bnws,
                                              const float* __restrict__ bnwb,
                                              const float* __restrict__ w2,
                                              const float* __restrict__ w2b)
{
  __shared__ float s_w1[8*128];
  __shared__ float s_w2[128*8];
  __shared__ float s_tb[8], s_ta[8];
  __shared__ float s_b2[128];
  int tid = threadIdx.x;
  for (int idx=tid; idx<1024; idx+=256){ s_w1[idx] = w1[idx]; s_w2[idx] = w2[idx]; }
  if (tid < 8){ float a = bnws[tid]; s_ta[tid] = a; s_tb[tid] = w1b[tid]*a + bnwb[tid]; }
  if (tid < 128) s_b2[tid] = w2b[tid];
  __syncthreads();

  int t = blockIdx.x*256 + tid;
  int b = t >> 12;
  int p = t & 4095;
  float2* fp = &g_f[(size_t)b*128*4096 + p];

  float acc[8];
  #pragma unroll
  for (int q=0;q<8;q++) acc[q] = 0.f;
  for (int c=0;c<128;c++){
    float r = fp[(size_t)c*4096].x;
    #pragma unroll
    for (int q=0;q<8;q++) acc[q] = fmaf(s_w1[q*128 + c], r, acc[q]);
  }
  float tq[8];
  #pragma unroll
  for (int q=0;q<8;q++) tq[q] = fmaxf(fmaf(acc[q], s_ta[q], s_tb[q]), 0.f);

  for (int c=0;c<128;c++){
    float s = s_b2[c];
    #pragma unroll
    for (int q=0;q<8;q++) s = fmaf(s_w2[c*8 + q], tq[q], s);
    float gate = 1.f / (1.f + __expf(-s));
    float2 fv = fp[(size_t)c*4096];
    fp[(size_t)c*4096] = make_float2(fv.x*gate, fv.y*gate);
  }
}

// ---------------- K8: spatial inverse fft2 of g*f + abs + residual ----------
__global__ void __launch_bounds__(512) k_ifft2sp(const float* __restrict__ x,
                                                 float* __restrict__ out){
  __shared__ float2 sc[64][FFT_PITCH];
  int bc = blockIdx.x;
  int tid = threadIdx.x;
  const float2* base = &g_f[(size_t)bc*4096];
  for (int idx=tid; idx<4096; idx+=512)
    sc[idx>>6][idx&63] = base[idx];
  __syncthreads();
  int g = tid>>3, l = tid&7;
  fft64v<1>(&sc[0][g], FFT_PITCH, l);
  fft64v<1>(&sc[g][0], 1,         l);
  int b = bc >> 7, c = bc & 127;
  const float* xb = &x[((size_t)b*256 + 128 + c)*4096];
  float* ob = &out[((size_t)b*256 + 128 + c)*4096];
  for (int idx=tid; idx<4096; idx+=512){
    float2 v = sc[idx>>6][idx&63];
    ob[idx] = sqrtf(v.x*v.x + v.y*v.y) * (1.f/4096.f) + xb[idx];
  }
}

// ---------------- launch (single stream, serial) ----------------
extern "C" void kernel_launch(void* const* d_in, const int* in_sizes, int n_in,
                              void* d_out, int out_size) {
  (void)in_sizes; (void)n_in; (void)out_size;
  const float* x     = (const float*)d_in[0];
  const float* c2w   = (const float*)d_in[1];
  const float* c2b   = (const float*)d_in[2];
  const float* bn2s  = (const float*)d_in[3];
  const float* bn2b  = (const float*)d_in[4];
  const float* temp  = (const float*)d_in[5];
  const float* w1w   = (const float*)d_in[6];
  const float* w1b   = (const float*)d_in[7];
  const float* bnws  = (const float*)d_in[8];
  const float* bnwb  = (const float*)d_in[9];
  const float* w2w   = (const float*)d_in[10];
  const float* w2b   = (const float*)d_in[11];
  float* out = (float*)d_out;

  const int SMEM_CONV = 3*32768;   // 96KB ring; epilogue reuses 67.6KB of it
  cudaFuncSetAttribute(k_conv_mma, cudaFuncAttributeMaxDynamicSharedMemorySize, SMEM_CONV);

  k_xprep<<<2048, 256>>>(x);
  k_wprep<<<576, 256>>>(c2w);
  k_conv_mma<<<512, 256, SMEM_CONV>>>(c2b, bn2s, bn2b);
  k_fft2<<<1024, 512>>>();
  k_gram_part<<<1024, 256>>>();
  k_gram_fin<<<128, 256>>>(temp);
  k_apply<<<1024, 256>>>();
  k_ifft4096<<<2048, 512>>>(x, out);
  k_gate<<<256, 256>>>(w1w, w1b, bnws, bnwb, w2w, w2b);
  k_ifft2sp<<<2048, 512>>>(x, out);
}